// round 14
// baseline (speedup 1.0000x reference)
#include <cuda_runtime.h>
#include <cuda_fp16.h>

#define TAGSETN 64
#define SEQN    512
#define NTAGS   66
#define STARTS  64
#define STOPS   65
#define LOG2E_F 1.4426950408889634f
#define LN2_F   0.6931471805599453f
#define OFFB    12.0f
#define NSEG    4
#define SEGL    128
#define WARM    16
#define BMAX    1024

#define BARS(id) asm volatile("bar.sync %0, %1;" :: "r"(id), "r"(64) : "memory")

__device__ float gI[BMAX][NSEG][TAGSETN];
__device__ float gO[BMAX][NSEG][TAGSETN];
__device__ float gNum[BMAX][NSEG];
__device__ int   gCnt[BMAX][NSEG];

__device__ __forceinline__ float ex2f(float x){float r;asm("ex2.approx.ftz.f32 %0, %1;":"=f"(r):"f"(x));return r;}
__device__ __forceinline__ float lg2f(float x){float r;asm("lg2.approx.ftz.f32 %0, %1;":"=f"(r):"f"(x));return r;}

__device__ __forceinline__ float dot64h(const __half* sa, const __half2* E2) {
    const uint4* p = (const uint4*)sa;
    const __half2 z = __floats2half2_rn(0.f, 0.f);
    __half2 c0 = z, c1 = z, c2 = z, c3 = z;
    #pragma unroll
    for (int q = 0; q < 8; ++q) {
        const uint4 u = p[q];
        c0 = __hfma2(*(const __half2*)&u.x, E2[4*q+0], c0);
        c1 = __hfma2(*(const __half2*)&u.y, E2[4*q+1], c1);
        c2 = __hfma2(*(const __half2*)&u.z, E2[4*q+2], c2);
        c3 = __hfma2(*(const __half2*)&u.w, E2[4*q+3], c3);
    }
    const float2 f = __half22float2(__hadd2(__hadd2(c0, c1), __hadd2(c2, c3)));
    return f.x + f.y;
}

// block = 128 thr = 2 independent 64-thread segment-chains (same batch).
// blk -> batch = blk>>1 ; segments {0,1} (blk even-half) or {2,3}.
__global__ __launch_bounds__(128, 7)
void crf_seg_kernel(const float* __restrict__ em,
                    const int*   __restrict__ tags,
                    const float* __restrict__ trans)
{
    const int blk   = blockIdx.x;
    const int batch = blk >> 1;
    const int tid   = threadIdx.x;
    const int half  = tid >> 6;
    const int seg   = ((blk & 1) << 1) | half;
    const int j     = tid & 63;
    const int lane  = tid & 31;
    const int wh    = (tid >> 5) & 1;
    const int bar   = half + 1;

    __shared__ __align__(16) __half sa[2][2][TAGSETN];  // [half][parity][state]
    __shared__ float sM[2][2];
    __shared__ float red[2][2];
    __shared__ int   icnt[2][2];
    __shared__ int   stags[SEQN];

    const float* emb = em + (size_t)batch * (SEQN * TAGSETN);

    #pragma unroll
    for (int q2 = 0; q2 < 4; ++q2)
        stags[tid + 128 * q2] = tags[batch * SEQN + tid + 128 * q2];
    __syncthreads();

    // E column j (fwd operator only — all chains are forward)
    __half2 E2[32];
    #pragma unroll
    for (int r = 0; r < 32; ++r)
        E2[r] = __floats2half2_rn(__expf(trans[(2*r  )*NTAGS + j]),
                                  __expf(trans[(2*r+1)*NTAGS + j]));

    const int s_k   = seg * SEGL;
    const int s_end = (seg == NSEG - 1) ? (SEQN - 1) : (s_k + SEGL);

    float a, lb, Mprev;
    int   t0;
    if (seg == 0) {
        const float Tst0 = __ldg(&trans[STARTS * NTAGS]);
        lb = (emb[j] + trans[STARTS*NTAGS + j] - Tst0) * LOG2E_F;
        float m = lb;
        #pragma unroll
        for (int o = 16; o; o >>= 1)
            m = fmaxf(m, __shfl_xor_sync(0xffffffffu, m, o));
        if (lane == 0) red[half][wh] = m;
        BARS(bar);
        Mprev = fmaxf(red[half][0], red[half][1]);
        a  = ex2f(lb - Mprev);
        t0 = 0;
    } else {
        // warm-start from uniform; direction converges at ~0.1/step (Birkhoff)
        a = 1.f; lb = 0.f; Mprev = 0.f;
        t0 = s_k - WARM;
    }

    float e_c = emb[(t0 + 1) * TAGSETN + j];
    int   t2  = (t0 + 2 <= s_end) ? t0 + 2 : s_end;
    int   t3  = (t0 + 3 <= s_end) ? t0 + 3 : s_end;
    float e_1 = emb[t2 * TAGSETN + j];
    float e_2 = emb[t3 * TAGSETN + j];
    int   tg_c = stags[t0 + 1];

    for (int t = t0 + 1; t <= s_end; ++t) {
        const float emL = e_c * LOG2E_F;
        __half* buf = sa[half][t & 1];
        buf[j] = __float2half_rn(a);
        if (j == 0) sM[half][t & 1] = lb + OFFB;
        BARS(bar);

        const float Mt = sM[half][t & 1];
        const float D  = Mprev - Mt;
        const float g  = ex2f(emL + D);
        const float h  = ex2f(D);

        const float s = dot64h(buf, E2);

        const bool mk = (tg_c != 0);
        a  = mk ? (s * g) : (a * h);
        lb = mk ? (emL + Mprev + lg2f(s)) : lb;
        Mprev = Mt;

        if (t == s_k)                       // end of warm-up: record I_k
            gI[batch][seg][j] = lg2f(a) + Mprev;

        e_c = e_1; e_1 = e_2;
        const int tn = (t + 3 <= s_end) ? (t + 3) : s_end;
        e_2 = emb[tn * TAGSETN + j];
        tg_c = stags[(t + 1 <= s_end) ? (t + 1) : s_end];
    }

    gO[batch][seg][j] = lg2f(a) + Mprev;    // O_k

    // ---- numerator over (s_k, s_end] (+ t=0 terms for seg 0) ----
    float acc = 0.f; int cnt = 0;
    for (int tt = s_k + 1 + j; tt <= s_end; tt += 64) {
        const int tg = stags[tt];
        if (tg != 0) {
            cnt += 1;
            acc += emb[tt * TAGSETN + tg] + trans[stags[tt-1] * NTAGS + tg];
        }
    }
    if (seg == 0 && j == 0) {
        const int tg0 = stags[0];
        acc += trans[STARTS * NTAGS + tg0];
        if (tg0 != 0) { acc += emb[tg0]; cnt += 1; }
    }
    #pragma unroll
    for (int o = 16; o; o >>= 1) {
        acc += __shfl_xor_sync(0xffffffffu, acc, o);
        cnt += __shfl_xor_sync(0xffffffffu, cnt, o);
    }
    if (lane == 0) { red[half][wh] = acc; icnt[half][wh] = cnt; }
    BARS(bar);
    if (j == 0) {
        gNum[batch][seg] = red[half][0] + red[half][1];
        gCnt[batch][seg] = icnt[half][0] + icnt[half][1];
    }
}

__global__ __launch_bounds__(64)
void crf_combine_kernel(const int*   __restrict__ tags,
                        const float* __restrict__ trans,
                        float*       __restrict__ out)
{
    const int b    = blockIdx.x;
    const int tid  = threadIdx.x;
    const int w    = tid >> 5;
    const int lane = tid & 31;

    __shared__ float lse[8];   // [0..3] = lse2(O0..O3), [4..6] = lse2(I1..I3)

    if (w == 0) {
        #pragma unroll
        for (int k = 0; k < 4; ++k) {
            const float x0 = gO[b][k][lane];
            const float x1 = gO[b][k][lane + 32];
            float m = fmaxf(x0, x1);
            #pragma unroll
            for (int o = 16; o; o >>= 1)
                m = fmaxf(m, __shfl_xor_sync(0xffffffffu, m, o));
            float s = ex2f(x0 - m) + ex2f(x1 - m);
            #pragma unroll
            for (int o = 16; o; o >>= 1)
                s += __shfl_xor_sync(0xffffffffu, s, o);
            if (lane == 0) lse[k] = m + lg2f(s);
        }
    } else {
        #pragma unroll
        for (int k = 1; k < 4; ++k) {
            const float x0 = gI[b][k][lane];
            const float x1 = gI[b][k][lane + 32];
            float m = fmaxf(x0, x1);
            #pragma unroll
            for (int o = 16; o; o >>= 1)
                m = fmaxf(m, __shfl_xor_sync(0xffffffffu, m, o));
            float s = ex2f(x0 - m) + ex2f(x1 - m);
            #pragma unroll
            for (int o = 16; o; o >>= 1)
                s += __shfl_xor_sync(0xffffffffu, s, o);
            if (lane == 0) lse[3 + k] = m + lg2f(s);
        }
    }
    __syncthreads();

    if (tid == 0) {
        // telescoped stitch of segment scale constants
        const float l2z = lse[3] - ((lse[4] - lse[0]) + (lse[5] - lse[1]) + (lse[6] - lse[2]));
        const float Tst0  = __ldg(&trans[STARTS * NTAGS]);
        const float Tend0 = __ldg(&trans[STOPS]);
        const float Cuni  = Tst0 + (float)(SEQN - 1) * Tend0;   // exact fp32
        const float log_z = Cuni + l2z * LN2_F;

        const float num = gNum[b][0] + gNum[b][1] + gNum[b][2] + gNum[b][3];
        const int   cnt = gCnt[b][0] + gCnt[b][1] + gCnt[b][2] + gCnt[b][3];
        int last = cnt - 1; if (last < 0) last = 0;
        const int ltag = tags[b * SEQN + last];
        out[b] = num + trans[ltag * NTAGS + STOPS] - log_z;
    }
}

extern "C" void kernel_launch(void* const* d_in, const int* in_sizes, int n_in,
                              void* d_out, int out_size)
{
    const float* emissions   = (const float*)d_in[0];
    const int*   tags        = (const int*)d_in[1];
    const float* transitions = (const float*)d_in[2];
    float*       out         = (float*)d_out;

    const int B = in_sizes[1] / SEQN;
    crf_seg_kernel<<<2 * B, 128>>>(emissions, tags, transitions);
    crf_combine_kernel<<<B, 64>>>(tags, transitions, out);
}

// round 16
// speedup vs baseline: 1.8112x; 1.8112x over previous
#include <cuda_runtime.h>
#include <cuda_fp16.h>

#define TAGSETN 64
#define SEQN    512
#define MIDT    256
#define NTAGS   66
#define STARTS  64
#define STOPS   65
#define LOG2E_F 1.4426950408889634f
#define LN2_F   0.6931471805599453f
#define OFFB    12.0f

#define BARS(id) asm volatile("bar.sync %0, %1;" :: "r"(id), "r"(64) : "memory")

__device__ __forceinline__ float ex2f(float x){float r;asm("ex2.approx.ftz.f32 %0, %1;":"=f"(r):"f"(x));return r;}
__device__ __forceinline__ float lg2f(float x){float r;asm("lg2.approx.ftz.f32 %0, %1;":"=f"(r):"f"(x));return r;}

__device__ __forceinline__ float dot64h(const __half* sa, const __half2* E2) {
    const uint4* p = (const uint4*)sa;
    const __half2 z = __floats2half2_rn(0.f, 0.f);
    __half2 c0 = z, c1 = z, c2 = z, c3 = z;
    #pragma unroll
    for (int q = 0; q < 8; ++q) {
        const uint4 u = p[q];
        c0 = __hfma2(*(const __half2*)&u.x, E2[4*q+0], c0);
        c1 = __hfma2(*(const __half2*)&u.y, E2[4*q+1], c1);
        c2 = __hfma2(*(const __half2*)&u.z, E2[4*q+2], c2);
        c3 = __hfma2(*(const __half2*)&u.w, E2[4*q+3], c3);
    }
    const float2 f = __half22float2(__hadd2(__hadd2(c0, c1), __hadd2(c2, c3)));
    return f.x + f.y;
}

__global__ __launch_bounds__(128, 7)
void crf_fused_kernel(const float* __restrict__ em,
                      const int*   __restrict__ tags,
                      const float* __restrict__ trans,
                      float*       __restrict__ out)
{
    const int b    = blockIdx.x;
    const int tid  = threadIdx.x;
    const int half = tid >> 6;          // 0 = forward, 1 = backward
    const int j    = tid & 63;
    const int lane = tid & 31;
    const int wh   = (tid >> 5) & 1;
    const int bar  = half + 1;

    __shared__ __align__(16) __half saF[2][TAGSETN], saB[2][TAGSETN];
    __shared__ float sMF[2], sMB[2];
    __shared__ float wredF[2];
    __shared__ float zred[2], zsum[2];
    __shared__ float nsum[2];
    __shared__ int   ncnt[2];
    __shared__ float sAlpha[TAGSETN], sBeta[TAGSETN];
    __shared__ int   stags[SEQN];

    const float* emb = em + (size_t)b * (SEQN * TAGSETN);

    #pragma unroll
    for (int q = 0; q < SEQN / 128; ++q)
        stags[tid + 128 * q] = tags[b * SEQN + tid + 128 * q];
    __syncthreads();

    __half2 E2[32];

    if (half == 0) {
        // ---------------- forward: alpha_0 .. alpha_256 ----------------
        #pragma unroll
        for (int r = 0; r < 32; ++r)
            E2[r] = __floats2half2_rn(__expf(trans[(2*r  )*NTAGS + j]),
                                      __expf(trans[(2*r+1)*NTAGS + j]));

        const float Tst_j = trans[STARTS * NTAGS + j];
        const float Tst0  = __ldg(&trans[STARTS * NTAGS + 0]);

        float lb = (emb[j] + Tst_j - Tst0) * LOG2E_F;

        float m0 = lb;
        #pragma unroll
        for (int o = 16; o; o >>= 1)
            m0 = fmaxf(m0, __shfl_xor_sync(0xffffffffu, m0, o));
        if (lane == 0) wredF[wh] = m0;
        BARS(1);
        float Mprev = fmaxf(wredF[0], wredF[1]);

        float a = ex2f(lb - Mprev);

        // prefetch depth 2 with running pointer (no clamps: reads <= em[258])
        float e_c = emb[1 * TAGSETN + j];
        float e_1 = emb[2 * TAGSETN + j];
        const float* pn = emb + 3 * TAGSETN + j;
        float pe = ex2f(e_c * LOG2E_F);
        int tg_c = stags[1];
        BARS(1);

        for (int t = 1; t <= MIDT; ++t) {
            __half* buf = saF[t & 1];
            buf[j] = __float2half_rn(a);
            if (j == 0) sMF[t & 1] = lb + OFFB;
            BARS(1);

            const float Mt = sMF[t & 1];
            const float h  = ex2f(Mprev - Mt);

            const float s  = dot64h(buf, E2);

            const bool mk = (tg_c != 0);
            a = mk ? s * (pe * h) : a * h;
            if (j == 0)
                lb = mk ? (fmaf(e_c, LOG2E_F, Mprev) + lg2f(s)) : lb;
            Mprev = Mt;

            e_c = e_1; e_1 = *pn; pn += TAGSETN;
            pe  = ex2f(e_c * LOG2E_F);
            tg_c = stags[t + 1];           // t+1 <= 257, in bounds
        }

        sAlpha[j] = lg2f(a) + Mprev;
    } else {
        // ---------------- backward: beta_511 .. beta_256 ----------------
        #pragma unroll
        for (int r = 0; r < 32; ++r)
            E2[r] = __floats2half2_rn(__expf(trans[j*NTAGS + 2*r    ]),
                                      __expf(trans[j*NTAGS + 2*r + 1]));

        float lb = 0.f, Mprev = 0.f, a = 1.f;

        float e_c = emb[511 * TAGSETN + j];
        float e_1 = emb[510 * TAGSETN + j];
        const float* pn = emb + 509 * TAGSETN + j;
        float pe = ex2f(e_c * LOG2E_F);
        int tg_c = stags[511];

        for (int t = 511; t >= 257; --t) {
            __half* buf = saB[t & 1];
            buf[j] = __float2half_rn(a * pe);      // fold emission pre-barrier
            if (j == 0) sMB[t & 1] = lb + OFFB;
            BARS(2);

            const float Mt = sMB[t & 1];
            const float h  = ex2f(Mprev - Mt);

            const float s  = dot64h(buf, E2);

            const bool mk = (tg_c != 0);
            a = (mk ? s : a) * h;
            if (j == 0)
                lb = mk ? (Mprev + lg2f(s)) : lb;
            Mprev = Mt;

            e_c = e_1; e_1 = *pn; pn -= TAGSETN;   // reads >= em[255], in bounds
            pe  = ex2f(e_c * LOG2E_F);
            tg_c = stags[t - 1];                   // t-1 >= 256, in bounds
        }

        sBeta[j] = lg2f(a) + Mprev;
    }

    __syncthreads();

    // ---------------- combine (both halves concurrent) ----------------
    if (half == 0) {
        const float v = sAlpha[j] + sBeta[j];
        float mz = v;
        #pragma unroll
        for (int o = 16; o; o >>= 1)
            mz = fmaxf(mz, __shfl_xor_sync(0xffffffffu, mz, o));
        if (lane == 0) zred[wh] = mz;
        BARS(1);
        const float Mz = fmaxf(zred[0], zred[1]);
        float az = ex2f(v - Mz);
        #pragma unroll
        for (int o = 16; o; o >>= 1)
            az += __shfl_xor_sync(0xffffffffu, az, o);
        if (lane == 0) zsum[wh] = az;
    } else {
        float acc = 0.f;
        int   cnt = 0;
        #pragma unroll
        for (int q = 0; q < SEQN / 64; ++q) {
            const int t  = j + 64 * q;
            const int tg = stags[t];
            const bool mk = (tg != 0);
            cnt += mk ? 1 : 0;
            if (t == 0) {
                acc += trans[STARTS * NTAGS + tg];
                if (mk) acc += emb[tg];
            } else if (mk) {
                acc += emb[t * TAGSETN + tg] + trans[stags[t-1] * NTAGS + tg];
            }
        }
        #pragma unroll
        for (int o = 16; o; o >>= 1) {
            acc += __shfl_xor_sync(0xffffffffu, acc, o);
            cnt += __shfl_xor_sync(0xffffffffu, cnt, o);
        }
        if (lane == 0) { nsum[wh] = acc; ncnt[wh] = cnt; }
    }

    __syncthreads();

    if (tid == 0) {
        const float Tst0  = __ldg(&trans[STARTS * NTAGS + 0]);
        const float Tend0 = __ldg(&trans[0 * NTAGS + STOPS]);
        const float Cuni  = Tst0 + (float)(SEQN - 1) * Tend0;
        const float log_z = Cuni + (fmaxf(zred[0], zred[1])
                            + lg2f(zsum[0] + zsum[1])) * LN2_F;
        const float accT  = nsum[0] + nsum[1];
        int last = (ncnt[0] + ncnt[1]) - 1;
        if (last < 0) last = 0;
        out[b] = accT + trans[stags[last] * NTAGS + STOPS] - log_z;
    }
}

extern "C" void kernel_launch(void* const* d_in, const int* in_sizes, int n_in,
                              void* d_out, int out_size)
{
    const float* emissions   = (const float*)d_in[0];
    const int*   tags        = (const int*)d_in[1];
    const float* transitions = (const float*)d_in[2];
    float*       out         = (float*)d_out;

    const int B = in_sizes[1] / SEQN;
    crf_fused_kernel<<<B, 128>>>(emissions, tags, transitions, out);
}